// round 17
// baseline (speedup 1.0000x reference)
#include <cuda_runtime.h>
#include <cuda_fp16.h>
#include <cstdint>

#define N_TASKS   8
#define D_MODEL   1024
#define HIDDEN    1024
#define N_CLASSES 100
#define BATCH     8192
#define KDIM      1024
#define LDSA      72
#define LDSB      136
#define LDSH      136
#define GRID1     296

// ===================== device scratch =====================
__device__ int g_count[N_TASKS], g_offset[N_TASKS];
__device__ __align__(16) int g_rows[BATCH];
__device__ int g_mt_task[80], g_mt_m0[80], g_nmt;
__device__ int g_done1[80];
__device__ int g_tile_ctr;
__device__ __align__(256) __half g_xh[BATCH * KDIM];              // ungrouped x fp16
__device__ __align__(256) __half g_w1h[N_TASKS * KDIM * HIDDEN];
__device__ __align__(256) __half g_w2h[N_TASKS * KDIM * 128];
__device__ __align__(256) __half g_hh[(BATCH + 128) * KDIM];      // grouped h fp16

// ===================== helpers =====================
__device__ __forceinline__ uint32_t smem_u32(const void* p) {
    uint32_t a;
    asm("{ .reg .u64 t; cvta.to.shared.u64 t, %1; cvt.u32.u64 %0, t; }" : "=r"(a) : "l"(p));
    return a;
}
__device__ __forceinline__ void ldm4(uint32_t& r0, uint32_t& r1, uint32_t& r2, uint32_t& r3,
                                     uint32_t addr) {
    asm volatile("ldmatrix.sync.aligned.m8n8.x4.shared.b16 {%0,%1,%2,%3}, [%4];"
                 : "=r"(r0), "=r"(r1), "=r"(r2), "=r"(r3) : "r"(addr));
}
__device__ __forceinline__ void ldm4t(uint32_t& r0, uint32_t& r1, uint32_t& r2, uint32_t& r3,
                                      uint32_t addr) {
    asm volatile("ldmatrix.sync.aligned.m8n8.x4.trans.shared.b16 {%0,%1,%2,%3}, [%4];"
                 : "=r"(r0), "=r"(r1), "=r"(r2), "=r"(r3) : "r"(addr));
}
__device__ __forceinline__ void mma16816(float* c, const uint32_t* a, const uint32_t* b) {
    asm volatile(
        "mma.sync.aligned.m16n8k16.row.col.f32.f16.f16.f32 "
        "{%0,%1,%2,%3}, {%4,%5,%6,%7}, {%8,%9}, {%0,%1,%2,%3};"
        : "+f"(c[0]), "+f"(c[1]), "+f"(c[2]), "+f"(c[3])
        : "r"(a[0]), "r"(a[1]), "r"(a[2]), "r"(a[3]), "r"(b[0]), "r"(b[1]));
}
__device__ __forceinline__ void cp16(uint32_t dst, const void* src) {
    asm volatile("cp.async.cg.shared.global [%0], [%1], 16;" :: "r"(dst), "l"(src) : "memory");
}
#define CP_COMMIT() asm volatile("cp.async.commit_group;" ::: "memory")
#define CP_WAIT0()  asm volatile("cp.async.wait_group 0;" ::: "memory")
template<int N> __device__ __forceinline__ void cp_wait() {
    asm volatile("cp.async.wait_group %0;" :: "n"(N) : "memory");
}

// ===================== fused convert + group: 4 regions =====================
#define GRP_BLKS 1
#define W1_BLKS  4096
#define W2_BLKS  512
#define X_BLKS   2048
__global__ __launch_bounds__(256)
void convert_all(const float* __restrict__ x,
                 const float* __restrict__ W1,
                 const float* __restrict__ W2,
                 const int* __restrict__ task_id) {
    const int bid = blockIdx.x;
    const int tid = threadIdx.x;
    if (bid == 0) {
        __shared__ uint64_t wlo[8], whi[8];
        __shared__ int s_off[N_TASKS];
        const int lane = tid & 31;
        const int wid  = tid >> 5;
        uint64_t lo = 0, hi = 0;
#pragma unroll 4
        for (int i = 0; i < 32; i++) {
            int t = task_id[tid * 32 + i];
            if (t < 4) lo += 1ull << (t * 16);
            else       hi += 1ull << ((t - 4) * 16);
        }
        uint64_t slo = lo, shi = hi;
#pragma unroll
        for (int d = 1; d < 32; d <<= 1) {
            uint64_t nlo = __shfl_up_sync(0xffffffffu, slo, d);
            uint64_t nhi = __shfl_up_sync(0xffffffffu, shi, d);
            if (lane >= d) { slo += nlo; shi += nhi; }
        }
        if (lane == 31) { wlo[wid] = slo; whi[wid] = shi; }
        __syncthreads();
        if (wid == 0 && lane < 8) {
            uint64_t a = wlo[lane], b = whi[lane];
#pragma unroll
            for (int d = 1; d < 8; d <<= 1) {
                uint64_t na = __shfl_up_sync(0xffu, a, d);
                uint64_t nb = __shfl_up_sync(0xffu, b, d);
                if (lane >= d) { a += na; b += nb; }
            }
            wlo[lane] = a; whi[lane] = b;
        }
        __syncthreads();
        if (tid == 0) {
            int tot[N_TASKS];
#pragma unroll
            for (int t = 0; t < 4; t++) tot[t] = (int)((wlo[7] >> (t * 16)) & 0xffff);
#pragma unroll
            for (int t = 4; t < 8; t++) tot[t] = (int)((whi[7] >> ((t - 4) * 16)) & 0xffff);
            int a = 0, nm = 0;
            for (int t = 0; t < N_TASKS; t++) {
                s_off[t] = a; g_offset[t] = a; g_count[t] = tot[t];
                for (int m0 = 0; m0 < tot[t]; m0 += 128) {
                    g_mt_task[nm] = t; g_mt_m0[nm] = m0; g_done1[nm] = 0; nm++;
                }
                a += tot[t];
            }
            g_nmt = nm;
            g_tile_ctr = 0;
        }
        __syncthreads();
        uint64_t elo = (wid ? wlo[wid - 1] : 0ull) + (slo - lo);
        uint64_t ehi = (wid ? whi[wid - 1] : 0ull) + (shi - hi);
#pragma unroll 4
        for (int i = 0; i < 32; i++) {
            const int t = task_id[tid * 32 + i];
            const int sh = (t & 3) * 16;
            int prior;
            if (t < 4) { prior = (int)((elo >> sh) & 0xffff); elo += 1ull << sh; }
            else       { prior = (int)((ehi >> sh) & 0xffff); ehi += 1ull << sh; }
            g_rows[s_off[t] + prior] = tid * 32 + i;
        }
    } else if (bid < GRP_BLKS + W1_BLKS) {
        const size_t i = ((size_t)(bid - GRP_BLKS) * 256 + tid) * 8;
        float4 v0 = ((const float4*)(W1 + i))[0];
        float4 v1 = ((const float4*)(W1 + i))[1];
        __half2 o[4];
        o[0] = __halves2half2(__float2half(v0.x), __float2half(v0.y));
        o[1] = __halves2half2(__float2half(v0.z), __float2half(v0.w));
        o[2] = __halves2half2(__float2half(v1.x), __float2half(v1.y));
        o[3] = __halves2half2(__float2half(v1.z), __float2half(v1.w));
        *(uint4*)(g_w1h + i) = *(uint4*)o;
    } else if (bid < GRP_BLKS + W1_BLKS + W2_BLKS) {
        const size_t e = ((size_t)(bid - GRP_BLKS - W1_BLKS) * 256 + tid) * 8;
        const int rk = (int)(e >> 7);
        const int n0 = (int)(e & 127);
        const float* src = W2 + (size_t)rk * N_CLASSES;
        __half2 o[4];
#pragma unroll
        for (int j = 0; j < 4; j++) {
            int na = n0 + 2 * j, nb = n0 + 2 * j + 1;
            float fa = (na < N_CLASSES) ? src[na] : 0.f;
            float fb = (nb < N_CLASSES) ? src[nb] : 0.f;
            o[j] = __halves2half2(__float2half(fa), __float2half(fb));
        }
        *(uint4*)(g_w2h + (size_t)rk * 128 + n0) = *(uint4*)o;
    } else {
        const size_t i = ((size_t)(bid - GRP_BLKS - W1_BLKS - W2_BLKS) * 256 + tid) * 16;
        float4 v0 = ((const float4*)(x + i))[0];
        float4 v1 = ((const float4*)(x + i))[1];
        float4 v2 = ((const float4*)(x + i))[2];
        float4 v3 = ((const float4*)(x + i))[3];
        __half2 o[8];
        o[0] = __halves2half2(__float2half(v0.x), __float2half(v0.y));
        o[1] = __halves2half2(__float2half(v0.z), __float2half(v0.w));
        o[2] = __halves2half2(__float2half(v1.x), __float2half(v1.y));
        o[3] = __halves2half2(__float2half(v1.z), __float2half(v1.w));
        o[4] = __halves2half2(__float2half(v2.x), __float2half(v2.y));
        o[5] = __halves2half2(__float2half(v2.z), __float2half(v2.w));
        o[6] = __halves2half2(__float2half(v3.x), __float2half(v3.y));
        o[7] = __halves2half2(__float2half(v3.z), __float2half(v3.w));
        uint4* dst = (uint4*)(g_xh + i);
        dst[0] = ((uint4*)o)[0];
        dst[1] = ((uint4*)o)[1];
    }
}

// ===================== GEMM core =====================
template<int BM, int BN, int BSTRIDE, int KCH, int NSTAGES, bool GATHER>
__device__ __forceinline__ void gemm_core(
    const __half* __restrict__ gA, const int* __restrict__ s_rows,
    const __half* __restrict__ gB,
    char* smem, float c[BM / 32][BN / 32][4])
{
    constexpr int MI = BM / 32, NI = BN / 32;
    constexpr int A_BYTES = BM * LDSA * 2;
    constexpr int B_BYTES = 64 * LDSB * 2;
    constexpr int STAGE_B = A_BYTES + B_BYTES;
    constexpr int UNITS_A = BM * 8;
    constexpr int UNITS_B = 64 * (BN / 8);
    constexpr int UNITS = UNITS_A + UNITS_B;

    const int tid  = threadIdx.x;
    const int lane = tid & 31;
    const int wid  = tid >> 5;
    const int wm   = wid & 1;
    const int wn   = wid >> 1;
    const uint32_t smem0 = smem_u32(smem);

    uint32_t eA[MI], eB[NI / 2];
#pragma unroll
    for (int mi = 0; mi < MI; mi++)
        eA[mi] = ((wm * (BM / 2) + mi * 16 + (lane & 15)) * LDSA + (lane >> 4) * 8) * 2;
    {
        const int g = lane >> 3, r = lane & 7;
        const int kl = (g & 1) * 8 + r;
#pragma unroll
        for (int j = 0; j < NI / 2; j++)
            eB[j] = (kl * LDSB + wn * (BN / 4) + j * 16 + (g >> 1) * 8) * 2;
    }

    auto issue = [&](int ch, int stage) {
        const int k = ch * 64;
        const uint32_t dA = smem0 + stage * STAGE_B;
        const uint32_t dB = dA + A_BYTES;
#pragma unroll
        for (int u = tid; u < UNITS; u += 256) {
            if (u < UNITS_A) {
                int row = u >> 3, seg = u & 7;
                size_t srow = GATHER ? (size_t)s_rows[row] : (size_t)row;
                cp16(dA + (row * LDSA + seg * 8) * 2, gA + srow * KDIM + k + seg * 8);
            } else {
                int v = u - UNITS_A;
                int kr = v / (BN / 8), seg = v % (BN / 8);
                cp16(dB + (kr * LDSB + seg * 8) * 2, gB + (size_t)(k + kr) * BSTRIDE + seg * 8);
            }
        }
    };

#pragma unroll
    for (int s = 0; s < NSTAGES - 1; s++) { issue(s, s); CP_COMMIT(); }

    for (int ch = 0; ch < KCH; ch++) {
        cp_wait<NSTAGES - 2>();
        __syncthreads();
        if (ch + NSTAGES - 1 < KCH) issue(ch + NSTAGES - 1, (ch + NSTAGES - 1) % NSTAGES);
        CP_COMMIT();

        const uint32_t bA = smem0 + (ch % NSTAGES) * STAGE_B;
        const uint32_t bB = bA + A_BYTES;
#pragma unroll
        for (int ks = 0; ks < 4; ks++) {
            uint32_t a[MI][4], b[NI][2];
#pragma unroll
            for (int mi = 0; mi < MI; mi++)
                ldm4(a[mi][0], a[mi][1], a[mi][2], a[mi][3], bA + eA[mi] + ks * 32);
#pragma unroll
            for (int j = 0; j < NI / 2; j++) {
                uint32_t r0, r1, r2, r3;
                ldm4t(r0, r1, r2, r3, bB + eB[j] + ks * (16 * LDSB * 2));
                b[2 * j][0] = r0; b[2 * j][1] = r1;
                b[2 * j + 1][0] = r2; b[2 * j + 1][1] = r3;
            }
#pragma unroll
            for (int mi = 0; mi < MI; mi++)
#pragma unroll
                for (int ni = 0; ni < NI; ni++)
                    mma16816(c[mi][ni], a[mi], b[ni]);
        }
    }
}

// ===================== fused persistent GEMM: layer1 tiles + inline layer2 =====================
#define STG1 3
#define SMEM1 (STG1 * (128 * LDSA + 64 * LDSB) * 2 + 512)
__global__ __launch_bounds__(256, 2)
void gemm_fused(const float* __restrict__ b1, const float* __restrict__ b2,
                float* __restrict__ out) {
    extern __shared__ char smem[];
    int* s_rows = (int*)(smem + STG1 * (128 * LDSA + 64 * LDSB) * 2);
    __half* hbuf = (__half*)smem;
    __shared__ int s_tile, s_old;
    const int ntotal = g_nmt * 8;

    const int tid  = threadIdx.x;
    const int lane = tid & 31;
    const int wid  = tid >> 5;
    const int wm = wid & 1, wn = wid >> 1;
    const int r4 = lane >> 2, c2 = (lane & 3) * 2;

    for (;;) {
        if (tid == 0) s_tile = atomicAdd(&g_tile_ctr, 1);
        __syncthreads();
        const int tile = s_tile;
        if (tile >= ntotal) return;
        const int e  = tile >> 3;
        const int n0 = (tile & 7) * 128;
        const int t  = g_mt_task[e];
        const int m0 = g_mt_m0[e];
        const int cnt = g_count[t];
        const int off = g_offset[t];

        if (tid < 128) {
            int m = m0 + tid;
            int idx = off + ((m < cnt) ? m : (cnt - 1));
            s_rows[tid] = g_rows[idx];
        }
        __syncthreads();

        float c[4][4][4];
#pragma unroll
        for (int mi = 0; mi < 4; mi++)
#pragma unroll
            for (int ni = 0; ni < 4; ni++)
#pragma unroll
                for (int r = 0; r < 4; r++) c[mi][ni][r] = 0.f;

        gemm_core<128, 128, HIDDEN, 16, STG1, true>(
            g_xh, s_rows, g_w1h + (size_t)t * KDIM * HIDDEN + n0, smem, c);

        CP_WAIT0();
        __syncthreads();

        // epilogue: bias+relu -> smem stage -> coalesced h store
        const float* b1t = b1 + t * HIDDEN + n0;
#pragma unroll
        for (int mi = 0; mi < 4; mi++) {
#pragma unroll
            for (int half = 0; half < 2; half++) {
                const int row = wm * 64 + mi * 16 + r4 + half * 8;
#pragma unroll
                for (int ni = 0; ni < 4; ni++) {
                    const int n = wn * 32 + ni * 8 + c2;
                    float v0 = fmaxf(c[mi][ni][half * 2 + 0] + b1t[n], 0.f);
                    float v1 = fmaxf(c[mi][ni][half * 2 + 1] + b1t[n + 1], 0.f);
                    *(__half2*)(hbuf + row * LDSH + n) =
                        __halves2half2(__float2half(v0), __float2half(v1));
                }
            }
        }
        __syncthreads();
#pragma unroll
        for (int u = tid; u < 2048; u += 256) {
            const int row = u >> 4, seg = u & 15;
            const int m = m0 + row;
            if (m < cnt)
                *(uint4*)(g_hh + (size_t)(off + m) * KDIM + n0 + seg * 8) =
                    *(const uint4*)(hbuf + row * LDSH + seg * 8);
        }
        __threadfence();            // release: h visible before counter bump
        __syncthreads();
        if (tid == 0) s_old = atomicAdd(&g_done1[e], 1);
        __syncthreads();

        if (s_old == 7) {
            // ---- all 8 n-tiles of m-tile e done: do its layer-2 GEMM inline ----
            __threadfence();        // acquire side
#pragma unroll
            for (int mi = 0; mi < 4; mi++)
#pragma unroll
                for (int ni = 0; ni < 4; ni++)
#pragma unroll
                    for (int r = 0; r < 4; r++) c[mi][ni][r] = 0.f;

            gemm_core<128, 128, 128, 16, STG1, false>(
                g_hh + (size_t)(off + m0) * KDIM, nullptr,
                g_w2h + (size_t)t * KDIM * 128, smem, c);

            const float* b2t = b2 + t * N_CLASSES;
#pragma unroll
            for (int mi = 0; mi < 4; mi++) {
#pragma unroll
                for (int half = 0; half < 2; half++) {
                    const int m = m0 + wm * 64 + mi * 16 + r4 + half * 8;
                    if (m < cnt) {
                        const int ro = g_rows[off + m];
                        float* orow = out + (size_t)ro * N_CLASSES;
#pragma unroll
                        for (int ni = 0; ni < 4; ni++) {
                            const int n = wn * 32 + ni * 8 + c2;
                            if (n < N_CLASSES)
                                orow[n] = c[mi][ni][half * 2 + 0] + b2t[n];
                            if (n + 1 < N_CLASSES)
                                orow[n + 1] = c[mi][ni][half * 2 + 1] + b2t[n + 1];
                        }
                    }
                }
            }
            CP_WAIT0();
            __syncthreads();
        }
    }
}

// ===================== launch =====================
extern "C" void kernel_launch(void* const* d_in, const int* in_sizes, int n_in,
                              void* d_out, int out_size) {
    const float* x       = (const float*)d_in[0];
    const int*   task_id = (const int*)d_in[1];
    const float* W1      = (const float*)d_in[2];
    const float* b1      = (const float*)d_in[3];
    const float* W2      = (const float*)d_in[4];
    const float* b2      = (const float*)d_in[5];
    float* out = (float*)d_out;

    static bool attr_done = false;
    if (!attr_done) {
        cudaFuncSetAttribute(gemm_fused, cudaFuncAttributeMaxDynamicSharedMemorySize, SMEM1);
        attr_done = true;
    }

    convert_all<<<GRP_BLKS + W1_BLKS + W2_BLKS + X_BLKS, 256>>>(x, W1, W2, task_id);
    gemm_fused<<<GRID1, 256, SMEM1>>>(b1, b2, out);
}